// round 14
// baseline (speedup 1.0000x reference)
#include <cuda_runtime.h>
#include <cuda_bf16.h>

#define NB 4
#define NN 384
#define HD 128
#define TQ 8
#define NTQ (NN/TQ)        // 48
#define SSPLIT 8
#define SCHUNK (NN/SSPLIT) // 48
#define NSB (SCHUNK/16)    // 3
#define NL 4
#define EPS 1e-5f
#define NROWS (NB*NN)      // 1536
#define GB (NROWS/8)       // 192 gemm blocks

// ---------------- scratch ----------------
__device__ float g_h   [NROWS*HD];
__device__ float g_xl  [NROWS*HD];
__device__ float g_xr  [NROWS*HD];
__device__ float g_ec  [20*HD];
__device__ float g_pacc[SSPLIT*NROWS*HD];
__device__ float g_pd  [SSPLIT*NROWS*8];

// ---------------- helpers ----------------
__device__ __forceinline__ float wsum(float v) {
    #pragma unroll
    for (int o = 16; o >= 1; o >>= 1) v += __shfl_xor_sync(0xffffffffu, v, o);
    return v;
}

// ---------------- embed: gather + LN1 + relu + GEMM(W_in) + LN2 ----------------
__global__ __launch_bounds__(256) void embed2_kernel(
        const int* __restrict__ x, const float* __restrict__ temb,
        const float* __restrict__ g1, const float* __restrict__ b1,
        const float* __restrict__ Win, const float* __restrict__ bin,
        const float* __restrict__ g2, const float* __restrict__ b2) {
    __shared__ float4 shx[128][2];
    __shared__ float  sho[8][128];
    __shared__ float  wred[8][4];
    __shared__ float  smean[8], srstd[8];
    __shared__ int    stok[8];
    int tid = threadIdx.x;
    int j = tid & 127, half = tid >> 7;
    int warp = tid >> 5, lane = tid & 31, q = warp & 3;
    int row0 = blockIdx.x * 8;

    if (tid < 8) stok[tid] = x[row0 + tid];
    __syncthreads();

    float v[4];
    #pragma unroll
    for (int rr = 0; rr < 4; rr++) v[rr] = temb[stok[half*4 + rr]*HD + j];

    // LN1: block reduce per row (mean)
    #pragma unroll
    for (int rr = 0; rr < 4; rr++) {
        float s = wsum(v[rr]);
        if (lane == 0) wred[half*4 + rr][q] = s;
    }
    __syncthreads();
    if (tid < 8) smean[tid] = (wred[tid][0]+wred[tid][1]+wred[tid][2]+wred[tid][3]) * (1.f/HD);
    __syncthreads();
    float d[4];
    #pragma unroll
    for (int rr = 0; rr < 4; rr++) {
        d[rr] = v[rr] - smean[half*4 + rr];
        float s = wsum(d[rr]*d[rr]);
        if (lane == 0) wred[half*4 + rr][q] = s;
    }
    __syncthreads();
    if (tid < 8) {
        float var = (wred[tid][0]+wred[tid][1]+wred[tid][2]+wred[tid][3]) * (1.f/HD);
        srstd[tid] = rsqrtf(var + EPS);
    }
    __syncthreads();
    float gj = g1[j], bj = b1[j];
    #pragma unroll
    for (int rr = 0; rr < 4; rr++) {
        float t = d[rr] * srstd[half*4 + rr] * gj + bj;
        v[rr] = fmaxf(t, 0.f);
    }
    shx[j][half] = make_float4(v[0], v[1], v[2], v[3]);
    __syncthreads();

    // GEMM: out[r][j] = sum_k shx[k][r] * Win[k][j] + bin[j]
    float bi = bin[j];
    float a0 = bi, a1 = bi, a2 = bi, a3 = bi;
    #pragma unroll 8
    for (int k = 0; k < HD; k++) {
        float w = Win[k*HD + j];
        float4 xk = shx[k][half];
        a0 = fmaf(xk.x, w, a0); a1 = fmaf(xk.y, w, a1);
        a2 = fmaf(xk.z, w, a2); a3 = fmaf(xk.w, w, a3);
    }
    sho[half*4 + 0][j] = a0; sho[half*4 + 1][j] = a1;
    sho[half*4 + 2][j] = a2; sho[half*4 + 3][j] = a3;
    __syncthreads();

    // LN2: warp per row
    {
        int r = warp;
        float4 f = *(const float4*)&sho[r][lane*4];
        float m = wsum(f.x + f.y + f.z + f.w) * (1.f/HD);
        f.x -= m; f.y -= m; f.z -= m; f.w -= m;
        float var = wsum(f.x*f.x + f.y*f.y + f.z*f.z + f.w*f.w) * (1.f/HD);
        float rs = rsqrtf(var + EPS);
        float4 gg = *(const float4*)&g2[lane*4];
        float4 bb = *(const float4*)&b2[lane*4];
        float4 o;
        o.x = f.x*rs*gg.x + bb.x; o.y = f.y*rs*gg.y + bb.y;
        o.z = f.z*rs*gg.z + bb.z; o.w = f.w*rs*gg.w + bb.w;
        *(float4*)&g_h[(row0 + r)*HD + lane*4] = o;
    }
}

// ---------------- lin: dual GEMM (Wl,Wr) + edge-cat tail ----------------
__global__ __launch_bounds__(256) void lin2_kernel(int l,
        const float* __restrict__ Wl, const float* __restrict__ bl,
        const float* __restrict__ Wr, const float* __restrict__ br,
        const float* __restrict__ We, const float* __restrict__ eemb) {
    __shared__ float4 shx[128][2];
    int tid = threadIdx.x;
    int j = tid & 127, half = tid >> 7;

    if (blockIdx.x < GB) {
        int row0 = blockIdx.x * 8;
        float v[4];
        #pragma unroll
        for (int rr = 0; rr < 4; rr++) v[rr] = g_h[(row0 + half*4 + rr)*HD + j];
        shx[j][half] = make_float4(v[0], v[1], v[2], v[3]);
        __syncthreads();

        const float* WlL = Wl + l*HD*HD;
        const float* WrL = Wr + l*HD*HD;
        float blj = bl[l*HD + j], brj = br[l*HD + j];
        float l0=blj,l1=blj,l2=blj,l3=blj;
        float r0=brj,r1=brj,r2=brj,r3=brj;
        #pragma unroll 8
        for (int k = 0; k < HD; k++) {
            float wl = WlL[k*HD + j];
            float wr = WrL[k*HD + j];
            float4 xk = shx[k][half];
            l0 = fmaf(xk.x, wl, l0); l1 = fmaf(xk.y, wl, l1);
            l2 = fmaf(xk.z, wl, l2); l3 = fmaf(xk.w, wl, l3);
            r0 = fmaf(xk.x, wr, r0); r1 = fmaf(xk.y, wr, r1);
            r2 = fmaf(xk.z, wr, r2); r3 = fmaf(xk.w, wr, r3);
        }
        int base = (row0 + half*4)*HD + j;
        g_xl[base        ] = l0; g_xl[base +   HD] = l1;
        g_xl[base + 2*HD ] = l2; g_xl[base + 3*HD] = l3;
        g_xr[base        ] = r0; g_xr[base +   HD] = r1;
        g_xr[base + 2*HD ] = r2; g_xr[base + 3*HD] = r3;
    } else {
        // edge-category projection: g_ec[cat] = eemb[cat] @ We[l]
        int row0 = (blockIdx.x - GB) * 8;
        float v[4];
        #pragma unroll
        for (int rr = 0; rr < 4; rr++) {
            int cat = row0 + half*4 + rr;
            v[rr] = (cat < 20) ? eemb[cat*HD + j] : 0.f;
        }
        shx[j][half] = make_float4(v[0], v[1], v[2], v[3]);
        __syncthreads();

        const float* WeL = We + l*HD*HD;
        float a0=0.f,a1=0.f,a2=0.f,a3=0.f;
        #pragma unroll 8
        for (int k = 0; k < HD; k++) {
            float w = WeL[k*HD + j];
            float4 xk = shx[k][half];
            a0 = fmaf(xk.x, w, a0); a1 = fmaf(xk.y, w, a1);
            a2 = fmaf(xk.z, w, a2); a3 = fmaf(xk.w, w, a3);
        }
        float acc[4] = {a0, a1, a2, a3};
        #pragma unroll
        for (int rr = 0; rr < 4; rr++) {
            int cat = row0 + half*4 + rr;
            if (cat < 20) g_ec[cat*HD + j] = acc[rr];
        }
    }
}

// ---------------- dense GATv2 attention: abs-decomposed leaky, all scalar ----------------
__global__ void attn_kernel(const float* __restrict__ att, int l) {
    __shared__ float z[TQ][5][132];     // xr[t] + ec[cat], 5 relevant cats per target
    __shared__ float xt[16][132];       // s-tile of xl
    __shared__ float wsm[8*16*8];       // [h][j(s-lane)][t]
    __shared__ float sB[TQ][5][8];      // 0.6 * att . z per (t,r,h)
    __shared__ float satt06[128];
    int blk = blockIdx.x;
    int split = blk & (SSPLIT-1);
    int tq = (blk >> 3) % NTQ;
    int b  = blk / (SSPLIT*NTQ);
    int t0 = tq * TQ;
    int tid = threadIdx.x;
    int lane = tid & 31;
    int sl = lane & 15;
    int h  = ((tid >> 5) << 1) + (lane >> 4);
    int hc = h << 4;
    const float* attL = att + l*HD;

    satt06[tid] = 0.6f * attL[tid];

    // build z table (float4 vectorized)
    for (int i = tid; i < TQ*5*32; i += 128) {
        int c4 = i & 31;
        int row = i >> 5;
        int t = row / 5, r = row - t*5;
        int pt = (t0 + t) & 3;
        int cat = (r < 4) ? (r*4 + pt) : (16 + pt);
        float4 xr4 = *(const float4*)(g_xr + (b*NN + t0 + t)*HD + c4*4);
        float4 ec4 = *(const float4*)(g_ec + cat*HD + c4*4);
        float4 o;
        o.x = xr4.x + ec4.x; o.y = xr4.y + ec4.y;
        o.z = xr4.z + ec4.z; o.w = xr4.w + ec4.w;
        *(float4*)&z[t][r][c4*4] = o;
    }
    __syncthreads();

    // sB table: sB[t][r][h] = sum_c 0.6*att[h,c] * z[t][r][h,c]
    for (int i = tid; i < TQ*5*8; i += 128) {
        int t = i / 40, qq = i - t*40;
        int r = qq >> 3, h2 = qq & 7;
        float dot = 0.f;
        #pragma unroll
        for (int c = 0; c < 16; c++) dot = fmaf(satt06[h2*16 + c], z[t][r][h2*16 + c], dot);
        sB[t][r][h2] = dot;
    }
    __syncthreads();

    // scalar attention coefficients (0.4x); A-term uses 0.6 = 1.5*0.4
    float a04[16];
    #pragma unroll
    for (int c4 = 0; c4 < 4; c4++) {
        float4 a = *(const float4*)(attL + hc + c4*4);
        a04[c4*4+0] = 0.4f*a.x; a04[c4*4+1] = 0.4f*a.y;
        a04[c4*4+2] = 0.4f*a.z; a04[c4*4+3] = 0.4f*a.w;
    }
    float acc[TQ], dp[TQ];
    #pragma unroll
    for (int t = 0; t < TQ; t++) { acc[t] = 0.f; dp[t] = 0.f; }

    int sbase = split * SCHUNK;
    for (int sb = 0; sb < NSB; sb++) {
        int s0 = sbase + sb*16;
        __syncthreads();
        // stage xl tile (coalesced)
        #pragma unroll
        for (int ii = 0; ii < 4; ii++) {
            int i = tid + ii*128;
            int r = i >> 5, c4 = i & 31;
            float4 v = *(const float4*)(g_xl + (b*NN + s0 + r)*HD + c4*4);
            *(float4*)&xt[r][c4*4] = v;
        }
        __syncthreads();

        // phase 1: lane role = (s = s0+sl, head h)
        int s = s0 + sl;
        int ps = sl & 3;
        float xlr[16];
        #pragma unroll
        for (int c4 = 0; c4 < 4; c4++) {
            float4 v = *(const float4*)&xt[sl][hc + c4*4];
            xlr[c4*4+0] = v.x; xlr[c4*4+1] = v.y; xlr[c4*4+2] = v.z; xlr[c4*4+3] = v.w;
        }
        float A0 = 0.f, A1 = 0.f;
        #pragma unroll
        for (int k = 0; k < 8; k++) {
            A0 = fmaf(a04[2*k],   xlr[2*k],   A0);
            A1 = fmaf(a04[2*k+1], xlr[2*k+1], A1);
        }
        float A = 1.5f * (A0 + A1);

        float w[TQ];
        #pragma unroll
        for (int t = 0; t < TQ; t++) {
            int r = (s == t0 + t) ? 4 : ps;
            const float* zp = &z[t][r][hc];
            float acc0 = 0.f, acc1 = 0.f;
            #pragma unroll
            for (int c4 = 0; c4 < 4; c4++) {
                float4 zz = *(const float4*)(zp + c4*4);
                acc0 = fmaf(a04[c4*4+0], fabsf(xlr[c4*4+0] + zz.x), acc0);
                acc1 = fmaf(a04[c4*4+1], fabsf(xlr[c4*4+1] + zz.y), acc1);
                acc0 = fmaf(a04[c4*4+2], fabsf(xlr[c4*4+2] + zz.z), acc0);
                acc1 = fmaf(a04[c4*4+3], fabsf(xlr[c4*4+3] + zz.w), acc1);
            }
            float e = __expf(A + sB[t][r][h] + acc0 + acc1);
            w[t] = e;
            dp[t] += e;
        }
        __syncwarp();
        *(float4*)&wsm[h*128 + sl*8]     = make_float4(w[0], w[1], w[2], w[3]);
        *(float4*)&wsm[h*128 + sl*8 + 4] = make_float4(w[4], w[5], w[6], w[7]);
        __syncwarp();

        // phase 2: lane role = (channel c = sl, head h); broadcast w via smem
        #pragma unroll
        for (int j = 0; j < 16; j++) {
            float xv = xt[j][hc + sl];
            float4 wa = *(const float4*)&wsm[h*128 + j*8];
            float4 wb = *(const float4*)&wsm[h*128 + j*8 + 4];
            acc[0] = fmaf(wa.x, xv, acc[0]); acc[1] = fmaf(wa.y, xv, acc[1]);
            acc[2] = fmaf(wa.z, xv, acc[2]); acc[3] = fmaf(wa.w, xv, acc[3]);
            acc[4] = fmaf(wb.x, xv, acc[4]); acc[5] = fmaf(wb.y, xv, acc[5]);
            acc[6] = fmaf(wb.z, xv, acc[6]); acc[7] = fmaf(wb.w, xv, acc[7]);
        }
        __syncwarp();
    }

    // reduce denominator over the 16 s-lanes
    #pragma unroll
    for (int t = 0; t < TQ; t++) {
        float d = dp[t];
        d += __shfl_xor_sync(0xffffffffu, d, 8, 16);
        d += __shfl_xor_sync(0xffffffffu, d, 4, 16);
        d += __shfl_xor_sync(0xffffffffu, d, 2, 16);
        d += __shfl_xor_sync(0xffffffffu, d, 1, 16);
        dp[t] = d;
    }
    int base = (split*NB + b)*NN + t0;
    #pragma unroll
    for (int t = 0; t < TQ; t++) {
        g_pacc[(base + t)*HD + hc + sl] = acc[t];
        if (sl == 0) g_pd[(base + t)*8 + h] = dp[t];
    }
}

// ---------------- proj: combine partials + GEMM(W_proj) + LN + relu + residual ----------------
__global__ __launch_bounds__(256) void proj2_kernel(int l,
        const float* __restrict__ bgat, const float* __restrict__ Wp,
        const float* __restrict__ bp,
        const float* __restrict__ lng, const float* __restrict__ lnb) {
    __shared__ float4 shx[128][2];
    __shared__ float  sho[8][128];
    __shared__ float  sdeninv[8][8];
    int tid = threadIdx.x;
    int j = tid & 127, half = tid >> 7;
    int warp = tid >> 5, lane = tid & 31;
    int row0 = blockIdx.x * 8;

    if (tid < 64) {
        int r = tid >> 3, hh = tid & 7;
        float dsum = 0.f;
        #pragma unroll
        for (int sp = 0; sp < SSPLIT; sp++)
            dsum += g_pd[(sp*NROWS + row0 + r)*8 + hh];
        sdeninv[r][hh] = 1.f / dsum;
    }
    __syncthreads();

    float bgj = bgat[l*HD + j];
    int hh = j >> 4;
    float v[4];
    #pragma unroll
    for (int rr = 0; rr < 4; rr++) {
        int node = row0 + half*4 + rr;
        float a = 0.f;
        #pragma unroll
        for (int sp = 0; sp < SSPLIT; sp++)
            a += g_pacc[(sp*NROWS + node)*HD + j];
        v[rr] = a * sdeninv[half*4 + rr][hh] + bgj;
    }
    shx[j][half] = make_float4(v[0], v[1], v[2], v[3]);
    __syncthreads();

    const float* WpL = Wp + l*HD*HD;
    float bpj = bp[l*HD + j];
    float a0=bpj,a1=bpj,a2=bpj,a3=bpj;
    #pragma unroll 8
    for (int k = 0; k < HD; k++) {
        float w = WpL[k*HD + j];
        float4 xk = shx[k][half];
        a0 = fmaf(xk.x, w, a0); a1 = fmaf(xk.y, w, a1);
        a2 = fmaf(xk.z, w, a2); a3 = fmaf(xk.w, w, a3);
    }
    sho[half*4 + 0][j] = a0; sho[half*4 + 1][j] = a1;
    sho[half*4 + 2][j] = a2; sho[half*4 + 3][j] = a3;
    __syncthreads();

    {
        int r = warp;
        float4 f = *(const float4*)&sho[r][lane*4];
        float m = wsum(f.x + f.y + f.z + f.w) * (1.f/HD);
        f.x -= m; f.y -= m; f.z -= m; f.w -= m;
        float var = wsum(f.x*f.x + f.y*f.y + f.z*f.z + f.w*f.w) * (1.f/HD);
        float rs = rsqrtf(var + EPS);
        float4 gg = *(const float4*)&lng[l*HD + lane*4];
        float4 bb = *(const float4*)&lnb[l*HD + lane*4];
        float4 hres = *(const float4*)&g_h[(row0 + r)*HD + lane*4];
        float4 o;
        o.x = fmaxf(f.x*rs*gg.x + bb.x, 0.f) + hres.x;
        o.y = fmaxf(f.y*rs*gg.y + bb.y, 0.f) + hres.y;
        o.z = fmaxf(f.z*rs*gg.z + bb.z, 0.f) + hres.z;
        o.w = fmaxf(f.w*rs*gg.w + bb.w, 0.f) + hres.w;
        *(float4*)&g_h[(row0 + r)*HD + lane*4] = o;
    }
}

// ---------------- node-sum + output head ----------------
__global__ __launch_bounds__(512) void out_kernel(const float* __restrict__ Wout,
                                                  const float* __restrict__ bout,
                                                  float* __restrict__ out) {
    __shared__ float sh[4][128];
    __shared__ float tot[128];
    int b = blockIdx.x, tid = threadIdx.x;
    int q = tid >> 7, c = tid & 127;
    float a = 0.f;
    #pragma unroll 8
    for (int n = q*96; n < q*96 + 96; n++) a += g_h[(b*NN + n)*HD + c];
    sh[q][c] = a;
    __syncthreads();
    if (tid < 128) tot[tid] = sh[0][tid] + sh[1][tid] + sh[2][tid] + sh[3][tid];
    __syncthreads();
    if (tid < 10) {
        float o = bout[tid];
        #pragma unroll 16
        for (int k = 0; k < HD; k++) o = fmaf(tot[k], Wout[k*10 + tid], o);
        out[b*10 + tid] = o;
    }
}

// ---------------- launch ----------------
extern "C" void kernel_launch(void* const* d_in, const int* in_sizes, int n_in,
                              void* d_out, int out_size) {
    const int*   x    = (const int*)  d_in[0];
    const float* temb = (const float*)d_in[4];
    const float* eemb = (const float*)d_in[5];
    const float* g1   = (const float*)d_in[6];
    const float* b1   = (const float*)d_in[7];
    const float* Win  = (const float*)d_in[8];
    const float* bin  = (const float*)d_in[9];
    const float* g2   = (const float*)d_in[10];
    const float* b2   = (const float*)d_in[11];
    const float* Wl   = (const float*)d_in[12];
    const float* bl   = (const float*)d_in[13];
    const float* Wr   = (const float*)d_in[14];
    const float* br   = (const float*)d_in[15];
    const float* We   = (const float*)d_in[16];
    const float* att  = (const float*)d_in[17];
    const float* bgat = (const float*)d_in[18];
    const float* Wp   = (const float*)d_in[19];
    const float* bp   = (const float*)d_in[20];
    const float* lng  = (const float*)d_in[21];
    const float* lnb  = (const float*)d_in[22];
    const float* Wout = (const float*)d_in[23];
    const float* bout = (const float*)d_in[24];
    float* out = (float*)d_out;

    embed2_kernel<<<GB, 256>>>(x, temb, g1, b1, Win, bin, g2, b2);
    for (int l = 0; l < NL; l++) {
        lin2_kernel<<<GB + 3, 256>>>(l, Wl, bl, Wr, br, We, eemb);
        attn_kernel<<<NB*NTQ*SSPLIT, 128>>>(att, l);
        proj2_kernel<<<GB, 256>>>(l, bgat, Wp, bp, lng, lnb);
    }
    out_kernel<<<NB, 512>>>(Wout, bout, out);
}

// round 15
// speedup vs baseline: 1.1071x; 1.1071x over previous
#include <cuda_runtime.h>
#include <cuda_bf16.h>

#define NB 4
#define NN 384
#define HD 128
#define TQ 8
#define NTQ (NN/TQ)        // 48
#define SSPLIT 8
#define SCHUNK (NN/SSPLIT) // 48
#define NSB (SCHUNK/16)    // 3
#define NL 4
#define EPS 1e-5f
#define NROWS (NB*NN)      // 1536
#define GB (NROWS/8)       // 192 gemm blocks
#define WROW 12            // padded wsm row stride (was 8): 4-way -> 2-way STS conflicts

// ---------------- scratch ----------------
__device__ float g_h   [NROWS*HD];
__device__ float g_xl  [NROWS*HD];
__device__ float g_xr  [NROWS*HD];
__device__ float g_ec  [20*HD];
__device__ float g_pacc[SSPLIT*NROWS*HD];
__device__ float g_pd  [SSPLIT*NROWS*8];

// ---------------- helpers ----------------
__device__ __forceinline__ float wsum(float v) {
    #pragma unroll
    for (int o = 16; o >= 1; o >>= 1) v += __shfl_xor_sync(0xffffffffu, v, o);
    return v;
}

// ---------------- embed: gather + LN1 + relu + GEMM(W_in) + LN2 ----------------
__global__ __launch_bounds__(256) void embed2_kernel(
        const int* __restrict__ x, const float* __restrict__ temb,
        const float* __restrict__ g1, const float* __restrict__ b1,
        const float* __restrict__ Win, const float* __restrict__ bin,
        const float* __restrict__ g2, const float* __restrict__ b2) {
    __shared__ float4 shx[128][2];
    __shared__ float  sho[8][128];
    __shared__ float  wred[8][4];
    __shared__ float  smean[8], srstd[8];
    __shared__ int    stok[8];
    int tid = threadIdx.x;
    int j = tid & 127, half = tid >> 7;
    int warp = tid >> 5, lane = tid & 31, q = warp & 3;
    int row0 = blockIdx.x * 8;

    if (tid < 8) stok[tid] = x[row0 + tid];
    __syncthreads();

    float v[4];
    #pragma unroll
    for (int rr = 0; rr < 4; rr++) v[rr] = temb[stok[half*4 + rr]*HD + j];

    // LN1: block reduce per row (mean)
    #pragma unroll
    for (int rr = 0; rr < 4; rr++) {
        float s = wsum(v[rr]);
        if (lane == 0) wred[half*4 + rr][q] = s;
    }
    __syncthreads();
    if (tid < 8) smean[tid] = (wred[tid][0]+wred[tid][1]+wred[tid][2]+wred[tid][3]) * (1.f/HD);
    __syncthreads();
    float d[4];
    #pragma unroll
    for (int rr = 0; rr < 4; rr++) {
        d[rr] = v[rr] - smean[half*4 + rr];
        float s = wsum(d[rr]*d[rr]);
        if (lane == 0) wred[half*4 + rr][q] = s;
    }
    __syncthreads();
    if (tid < 8) {
        float var = (wred[tid][0]+wred[tid][1]+wred[tid][2]+wred[tid][3]) * (1.f/HD);
        srstd[tid] = rsqrtf(var + EPS);
    }
    __syncthreads();
    float gj = g1[j], bj = b1[j];
    #pragma unroll
    for (int rr = 0; rr < 4; rr++) {
        float t = d[rr] * srstd[half*4 + rr] * gj + bj;
        v[rr] = fmaxf(t, 0.f);
    }
    shx[j][half] = make_float4(v[0], v[1], v[2], v[3]);
    __syncthreads();

    // GEMM: out[r][j] = sum_k shx[k][r] * Win[k][j] + bin[j]
    float bi = bin[j];
    float a0 = bi, a1 = bi, a2 = bi, a3 = bi;
    #pragma unroll 8
    for (int k = 0; k < HD; k++) {
        float w = Win[k*HD + j];
        float4 xk = shx[k][half];
        a0 = fmaf(xk.x, w, a0); a1 = fmaf(xk.y, w, a1);
        a2 = fmaf(xk.z, w, a2); a3 = fmaf(xk.w, w, a3);
    }
    sho[half*4 + 0][j] = a0; sho[half*4 + 1][j] = a1;
    sho[half*4 + 2][j] = a2; sho[half*4 + 3][j] = a3;
    __syncthreads();

    // LN2: warp per row
    {
        int r = warp;
        float4 f = *(const float4*)&sho[r][lane*4];
        float m = wsum(f.x + f.y + f.z + f.w) * (1.f/HD);
        f.x -= m; f.y -= m; f.z -= m; f.w -= m;
        float var = wsum(f.x*f.x + f.y*f.y + f.z*f.z + f.w*f.w) * (1.f/HD);
        float rs = rsqrtf(var + EPS);
        float4 gg = *(const float4*)&g2[lane*4];
        float4 bb = *(const float4*)&b2[lane*4];
        float4 o;
        o.x = f.x*rs*gg.x + bb.x; o.y = f.y*rs*gg.y + bb.y;
        o.z = f.z*rs*gg.z + bb.z; o.w = f.w*rs*gg.w + bb.w;
        *(float4*)&g_h[(row0 + r)*HD + lane*4] = o;
    }
}

// ---------------- lin: dual GEMM (Wl,Wr) + edge-cat tail ----------------
__global__ __launch_bounds__(256) void lin2_kernel(int l,
        const float* __restrict__ Wl, const float* __restrict__ bl,
        const float* __restrict__ Wr, const float* __restrict__ br,
        const float* __restrict__ We, const float* __restrict__ eemb) {
    __shared__ float4 shx[128][2];
    int tid = threadIdx.x;
    int j = tid & 127, half = tid >> 7;

    if (blockIdx.x < GB) {
        int row0 = blockIdx.x * 8;
        float v[4];
        #pragma unroll
        for (int rr = 0; rr < 4; rr++) v[rr] = g_h[(row0 + half*4 + rr)*HD + j];
        shx[j][half] = make_float4(v[0], v[1], v[2], v[3]);
        __syncthreads();

        const float* WlL = Wl + l*HD*HD;
        const float* WrL = Wr + l*HD*HD;
        float blj = bl[l*HD + j], brj = br[l*HD + j];
        float l0=blj,l1=blj,l2=blj,l3=blj;
        float r0=brj,r1=brj,r2=brj,r3=brj;
        #pragma unroll 8
        for (int k = 0; k < HD; k++) {
            float wl = WlL[k*HD + j];
            float wr = WrL[k*HD + j];
            float4 xk = shx[k][half];
            l0 = fmaf(xk.x, wl, l0); l1 = fmaf(xk.y, wl, l1);
            l2 = fmaf(xk.z, wl, l2); l3 = fmaf(xk.w, wl, l3);
            r0 = fmaf(xk.x, wr, r0); r1 = fmaf(xk.y, wr, r1);
            r2 = fmaf(xk.z, wr, r2); r3 = fmaf(xk.w, wr, r3);
        }
        int base = (row0 + half*4)*HD + j;
        g_xl[base        ] = l0; g_xl[base +   HD] = l1;
        g_xl[base + 2*HD ] = l2; g_xl[base + 3*HD] = l3;
        g_xr[base        ] = r0; g_xr[base +   HD] = r1;
        g_xr[base + 2*HD ] = r2; g_xr[base + 3*HD] = r3;
    } else {
        // edge-category projection: g_ec[cat] = eemb[cat] @ We[l]
        int row0 = (blockIdx.x - GB) * 8;
        float v[4];
        #pragma unroll
        for (int rr = 0; rr < 4; rr++) {
            int cat = row0 + half*4 + rr;
            v[rr] = (cat < 20) ? eemb[cat*HD + j] : 0.f;
        }
        shx[j][half] = make_float4(v[0], v[1], v[2], v[3]);
        __syncthreads();

        const float* WeL = We + l*HD*HD;
        float a0=0.f,a1=0.f,a2=0.f,a3=0.f;
        #pragma unroll 8
        for (int k = 0; k < HD; k++) {
            float w = WeL[k*HD + j];
            float4 xk = shx[k][half];
            a0 = fmaf(xk.x, w, a0); a1 = fmaf(xk.y, w, a1);
            a2 = fmaf(xk.z, w, a2); a3 = fmaf(xk.w, w, a3);
        }
        float acc[4] = {a0, a1, a2, a3};
        #pragma unroll
        for (int rr = 0; rr < 4; rr++) {
            int cat = row0 + half*4 + rr;
            if (cat < 20) g_ec[cat*HD + j] = acc[rr];
        }
    }
}

// ---------------- dense GATv2 attention (partial softmax over s-chunks) ----------------
__global__ void attn_kernel(const float* __restrict__ att, int l) {
    __shared__ float z[TQ][5][132];     // xr[t] + ec[cat], 5 relevant cats per target
    __shared__ float xt[16][132];       // s-tile of xl
    __shared__ float wsm[8*16*WROW];    // [h][j(s-lane)][t], padded rows
    int blk = blockIdx.x;
    int split = blk & (SSPLIT-1);
    int tq = (blk >> 3) % NTQ;
    int b  = blk / (SSPLIT*NTQ);
    int t0 = tq * TQ;
    int tid = threadIdx.x;
    int lane = tid & 31;
    int sl = lane & 15;
    int h  = ((tid >> 5) << 1) + (lane >> 4);
    int hc = h << 4;
    const float* attL = att + l*HD;

    // build z table (float4 vectorized: rows are float4-aligned since 132 % 4 == 0)
    for (int i = tid; i < TQ*5*32; i += 128) {
        int c4 = i & 31;
        int row = i >> 5;
        int t = row / 5, r = row - t*5;
        int pt = (t0 + t) & 3;
        int cat = (r < 4) ? (r*4 + pt) : (16 + pt);
        float4 xr4 = *(const float4*)(g_xr + (b*NN + t0 + t)*HD + c4*4);
        float4 ec4 = *(const float4*)(g_ec + cat*HD + c4*4);
        float4 o;
        o.x = xr4.x + ec4.x; o.y = xr4.y + ec4.y;
        o.z = xr4.z + ec4.z; o.w = xr4.w + ec4.w;
        *(float4*)&z[t][r][c4*4] = o;
    }
    float attr[16];
    #pragma unroll
    for (int c4 = 0; c4 < 4; c4++) {
        float4 a = *(const float4*)(attL + hc + c4*4);
        attr[c4*4+0] = a.x; attr[c4*4+1] = a.y; attr[c4*4+2] = a.z; attr[c4*4+3] = a.w;
    }
    float acc[TQ], dp[TQ];
    #pragma unroll
    for (int t = 0; t < TQ; t++) { acc[t] = 0.f; dp[t] = 0.f; }

    int sbase = split * SCHUNK;
    for (int sb = 0; sb < NSB; sb++) {
        int s0 = sbase + sb*16;
        __syncthreads();
        // stage xl tile (coalesced)
        #pragma unroll
        for (int ii = 0; ii < 4; ii++) {
            int i = tid + ii*128;
            int r = i >> 5, c4 = i & 31;
            float4 v = *(const float4*)(g_xl + (b*NN + s0 + r)*HD + c4*4);
            *(float4*)&xt[r][c4*4] = v;
        }
        __syncthreads();

        // phase 1: lane role = (s = s0+sl, head h); full logit in registers
        int s = s0 + sl;
        int ps = sl & 3;
        float xlr[16];
        #pragma unroll
        for (int c4 = 0; c4 < 4; c4++) {
            float4 v = *(const float4*)&xt[sl][hc + c4*4];
            xlr[c4*4+0] = v.x; xlr[c4*4+1] = v.y; xlr[c4*4+2] = v.z; xlr[c4*4+3] = v.w;
        }
        float w[TQ];
        #pragma unroll
        for (int t = 0; t < TQ; t++) {
            int r = (s == t0 + t) ? 4 : ps;
            const float* zp = &z[t][r][hc];
            float logit = 0.f;
            #pragma unroll
            for (int c4 = 0; c4 < 4; c4++) {
                float4 zz = *(const float4*)(zp + c4*4);
                float u;
                u = xlr[c4*4+0] + zz.x; u = fmaxf(u, 0.2f*u); logit = fmaf(u, attr[c4*4+0], logit);
                u = xlr[c4*4+1] + zz.y; u = fmaxf(u, 0.2f*u); logit = fmaf(u, attr[c4*4+1], logit);
                u = xlr[c4*4+2] + zz.z; u = fmaxf(u, 0.2f*u); logit = fmaf(u, attr[c4*4+2], logit);
                u = xlr[c4*4+3] + zz.w; u = fmaxf(u, 0.2f*u); logit = fmaf(u, attr[c4*4+3], logit);
            }
            float e = __expf(logit);   // logits are O(1): no max-subtraction needed
            w[t] = e;
            dp[t] += e;
        }
        __syncwarp();
        *(float4*)&wsm[(h*16 + sl)*WROW]     = make_float4(w[0], w[1], w[2], w[3]);
        *(float4*)&wsm[(h*16 + sl)*WROW + 4] = make_float4(w[4], w[5], w[6], w[7]);
        __syncwarp();

        // phase 2: lane role = (channel c = sl, head h); broadcast w via smem
        #pragma unroll
        for (int j = 0; j < 16; j++) {
            float xv = xt[j][hc + sl];
            float4 wa = *(const float4*)&wsm[(h*16 + j)*WROW];
            float4 wb = *(const float4*)&wsm[(h*16 + j)*WROW + 4];
            acc[0] = fmaf(wa.x, xv, acc[0]); acc[1] = fmaf(wa.y, xv, acc[1]);
            acc[2] = fmaf(wa.z, xv, acc[2]); acc[3] = fmaf(wa.w, xv, acc[3]);
            acc[4] = fmaf(wb.x, xv, acc[4]); acc[5] = fmaf(wb.y, xv, acc[5]);
            acc[6] = fmaf(wb.z, xv, acc[6]); acc[7] = fmaf(wb.w, xv, acc[7]);
        }
        __syncwarp();
    }

    // reduce denominator over the 16 s-lanes
    #pragma unroll
    for (int t = 0; t < TQ; t++) {
        float d = dp[t];
        d += __shfl_xor_sync(0xffffffffu, d, 8, 16);
        d += __shfl_xor_sync(0xffffffffu, d, 4, 16);
        d += __shfl_xor_sync(0xffffffffu, d, 2, 16);
        d += __shfl_xor_sync(0xffffffffu, d, 1, 16);
        dp[t] = d;
    }
    int base = (split*NB + b)*NN + t0;
    #pragma unroll
    for (int t = 0; t < TQ; t++) {
        g_pacc[(base + t)*HD + hc + sl] = acc[t];
        if (sl == 0) g_pd[(base + t)*8 + h] = dp[t];
    }
}

// ---------------- proj: combine partials + GEMM(W_proj) + LN + relu + residual ----------------
__global__ __launch_bounds__(256) void proj2_kernel(int l,
        const float* __restrict__ bgat, const float* __restrict__ Wp,
        const float* __restrict__ bp,
        const float* __restrict__ lng, const float* __restrict__ lnb) {
    __shared__ float4 shx[128][2];
    __shared__ float  sho[8][128];
    __shared__ float  sdeninv[8][8];
    int tid = threadIdx.x;
    int j = tid & 127, half = tid >> 7;
    int warp = tid >> 5, lane = tid & 31;
    int row0 = blockIdx.x * 8;

    if (tid < 64) {
        int r = tid >> 3, hh = tid & 7;
        float dsum = 0.f;
        #pragma unroll
        for (int sp = 0; sp < SSPLIT; sp++)
            dsum += g_pd[(sp*NROWS + row0 + r)*8 + hh];
        sdeninv[r][hh] = 1.f / dsum;
    }
    __syncthreads();

    float bgj = bgat[l*HD + j];
    int hh = j >> 4;
    float v[4];
    #pragma unroll
    for (int rr = 0; rr < 4; rr++) {
        int node = row0 + half*4 + rr;
        float a = 0.f;
        #pragma unroll
        for (int sp = 0; sp < SSPLIT; sp++)
            a += g_pacc[(sp*NROWS + node)*HD + j];
        v[rr] = a * sdeninv[half*4 + rr][hh] + bgj;
    }
    shx[j][half] = make_float4(v[0], v[1], v[2], v[3]);
    __syncthreads();

    const float* WpL = Wp + l*HD*HD;
    float bpj = bp[l*HD + j];
    float a0=bpj,a1=bpj,a2=bpj,a3=bpj;
    #pragma unroll 8
    for (int k = 0; k < HD; k++) {
        float w = WpL[k*HD + j];
        float4 xk = shx[k][half];
        a0 = fmaf(xk.x, w, a0); a1 = fmaf(xk.y, w, a1);
        a2 = fmaf(xk.z, w, a2); a3 = fmaf(xk.w, w, a3);
    }
    sho[half*4 + 0][j] = a0; sho[half*4 + 1][j] = a1;
    sho[half*4 + 2][j] = a2; sho[half*4 + 3][j] = a3;
    __syncthreads();

    {
        int r = warp;
        float4 f = *(const float4*)&sho[r][lane*4];
        float m = wsum(f.x + f.y + f.z + f.w) * (1.f/HD);
        f.x -= m; f.y -= m; f.z -= m; f.w -= m;
        float var = wsum(f.x*f.x + f.y*f.y + f.z*f.z + f.w*f.w) * (1.f/HD);
        float rs = rsqrtf(var + EPS);
        float4 gg = *(const float4*)&lng[l*HD + lane*4];
        float4 bb = *(const float4*)&lnb[l*HD + lane*4];
        float4 hres = *(const float4*)&g_h[(row0 + r)*HD + lane*4];
        float4 o;
        o.x = fmaxf(f.x*rs*gg.x + bb.x, 0.f) + hres.x;
        o.y = fmaxf(f.y*rs*gg.y + bb.y, 0.f) + hres.y;
        o.z = fmaxf(f.z*rs*gg.z + bb.z, 0.f) + hres.z;
        o.w = fmaxf(f.w*rs*gg.w + bb.w, 0.f) + hres.w;
        *(float4*)&g_h[(row0 + r)*HD + lane*4] = o;
    }
}

// ---------------- node-sum + output head ----------------
__global__ __launch_bounds__(512) void out_kernel(const float* __restrict__ Wout,
                                                  const float* __restrict__ bout,
                                                  float* __restrict__ out) {
    __shared__ float sh[4][128];
    __shared__ float tot[128];
    int b = blockIdx.x, tid = threadIdx.x;
    int q = tid >> 7, c = tid & 127;
    float a = 0.f;
    #pragma unroll 8
    for (int n = q*96; n < q*96 + 96; n++) a += g_h[(b*NN + n)*HD + c];
    sh[q][c] = a;
    __syncthreads();
    if (tid < 128) tot[tid] = sh[0][tid] + sh[1][tid] + sh[2][tid] + sh[3][tid];
    __syncthreads();
    if (tid < 10) {
        float o = bout[tid];
        #pragma unroll 16
        for (int k = 0; k < HD; k++) o = fmaf(tot[k], Wout[k*10 + tid], o);
        out[b*10 + tid] = o;
    }
}

// ---------------- launch ----------------
extern "C" void kernel_launch(void* const* d_in, const int* in_sizes, int n_in,
                              void* d_out, int out_size) {
    const int*   x    = (const int*)  d_in[0];
    const float* temb = (const float*)d_in[4];
    const float* eemb = (const float*)d_in[5];
    const float* g1   = (const float*)d_in[6];
    const float* b1   = (const float*)d_in[7];
    const float* Win  = (const float*)d_in[8];
    const float* bin  = (const float*)d_in[9];
    const float* g2   = (const float*)d_in[10];
    const float* b2   = (const float*)d_in[11];
    const float* Wl   = (const float*)d_in[12];
    const float* bl   = (const float*)d_in[13];
    const float* Wr   = (const float*)d_in[14];
    const float* br   = (const float*)d_in[15];
    const float* We   = (const float*)d_in[16];
    const float* att  = (const float*)d_in[17];
    const float* bgat = (const float*)d_in[18];
    const float* Wp   = (const float*)d_in[19];
    const float* bp   = (const float*)d_in[20];
    const float* lng  = (const float*)d_in[21];
    const float* lnb  = (const float*)d_in[22];
    const float* Wout = (const float*)d_in[23];
    const float* bout = (const float*)d_in[24];
    float* out = (float*)d_out;

    embed2_kernel<<<GB, 256>>>(x, temb, g1, b1, Win, bin, g2, b2);
    for (int l = 0; l < NL; l++) {
        lin2_kernel<<<GB + 3, 256>>>(l, Wl, bl, Wr, br, We, eemb);
        attn_kernel<<<NB*NTQ*SSPLIT, 128>>>(att, l);
        proj2_kernel<<<GB, 256>>>(l, bgat, Wp, bp, lng, lnb);
    }
    out_kernel<<<NB, 512>>>(Wout, bout, out);
}

// round 17
// speedup vs baseline: 1.1444x; 1.0337x over previous
#include <cuda_runtime.h>
#include <cuda_bf16.h>

#define NB 4
#define NN 384
#define HD 128
#define TQ 8
#define NTQ (NN/TQ)        // 48
#define SSPLIT 8
#define SCHUNK (NN/SSPLIT) // 48
#define NSB (SCHUNK/16)    // 3
#define NL 4
#define EPS 1e-5f
#define NROWS (NB*NN)      // 1536
#define GB (NROWS/8)       // 192 gemm blocks
#define WROW 12            // padded wsm row stride: 4-way -> 2-way STS conflicts

// ---------------- scratch ----------------
__device__ float g_h   [NROWS*HD];
__device__ float g_xl  [NROWS*HD];
__device__ float g_xr  [NROWS*HD];
__device__ float g_ec  [20*HD];
__device__ float g_pacc[SSPLIT*NROWS*HD];
__device__ float g_pd  [SSPLIT*NROWS*8];

// ---------------- helpers ----------------
__device__ __forceinline__ float wsum(float v) {
    #pragma unroll
    for (int o = 16; o >= 1; o >>= 1) v += __shfl_xor_sync(0xffffffffu, v, o);
    return v;
}
__device__ __forceinline__ void cpasync16(unsigned int saddr, const float* gptr) {
    asm volatile("cp.async.cg.shared.global [%0], [%1], 16;" :: "r"(saddr), "l"(gptr));
}
#define CP_COMMIT() asm volatile("cp.async.commit_group;" ::: "memory")
#define CP_WAIT0()  asm volatile("cp.async.wait_group 0;" ::: "memory")

// ---------------- embed: gather + LN1 + relu + GEMM(W_in) + LN2 ----------------
__global__ __launch_bounds__(256) void embed2_kernel(
        const int* __restrict__ x, const float* __restrict__ temb,
        const float* __restrict__ g1, const float* __restrict__ b1,
        const float* __restrict__ Win, const float* __restrict__ bin,
        const float* __restrict__ g2, const float* __restrict__ b2) {
    __shared__ float4 shx[128][2];
    __shared__ float  sho[8][128];
    __shared__ float  wred[8][4];
    __shared__ float  smean[8], srstd[8];
    __shared__ int    stok[8];
    int tid = threadIdx.x;
    int j = tid & 127, half = tid >> 7;
    int warp = tid >> 5, lane = tid & 31, q = warp & 3;
    int row0 = blockIdx.x * 8;

    if (tid < 8) stok[tid] = x[row0 + tid];
    __syncthreads();

    float v[4];
    #pragma unroll
    for (int rr = 0; rr < 4; rr++) v[rr] = temb[stok[half*4 + rr]*HD + j];

    #pragma unroll
    for (int rr = 0; rr < 4; rr++) {
        float s = wsum(v[rr]);
        if (lane == 0) wred[half*4 + rr][q] = s;
    }
    __syncthreads();
    if (tid < 8) smean[tid] = (wred[tid][0]+wred[tid][1]+wred[tid][2]+wred[tid][3]) * (1.f/HD);
    __syncthreads();
    float d[4];
    #pragma unroll
    for (int rr = 0; rr < 4; rr++) {
        d[rr] = v[rr] - smean[half*4 + rr];
        float s = wsum(d[rr]*d[rr]);
        if (lane == 0) wred[half*4 + rr][q] = s;
    }
    __syncthreads();
    if (tid < 8) {
        float var = (wred[tid][0]+wred[tid][1]+wred[tid][2]+wred[tid][3]) * (1.f/HD);
        srstd[tid] = rsqrtf(var + EPS);
    }
    __syncthreads();
    float gj = g1[j], bj = b1[j];
    #pragma unroll
    for (int rr = 0; rr < 4; rr++) {
        float t = d[rr] * srstd[half*4 + rr] * gj + bj;
        v[rr] = fmaxf(t, 0.f);
    }
    shx[j][half] = make_float4(v[0], v[1], v[2], v[3]);
    __syncthreads();

    float bi = bin[j];
    float a0 = bi, a1 = bi, a2 = bi, a3 = bi;
    #pragma unroll 8
    for (int k = 0; k < HD; k++) {
        float w = Win[k*HD + j];
        float4 xk = shx[k][half];
        a0 = fmaf(xk.x, w, a0); a1 = fmaf(xk.y, w, a1);
        a2 = fmaf(xk.z, w, a2); a3 = fmaf(xk.w, w, a3);
    }
    sho[half*4 + 0][j] = a0; sho[half*4 + 1][j] = a1;
    sho[half*4 + 2][j] = a2; sho[half*4 + 3][j] = a3;
    __syncthreads();

    {
        int r = warp;
        float4 f = *(const float4*)&sho[r][lane*4];
        float m = wsum(f.x + f.y + f.z + f.w) * (1.f/HD);
        f.x -= m; f.y -= m; f.z -= m; f.w -= m;
        float var = wsum(f.x*f.x + f.y*f.y + f.z*f.z + f.w*f.w) * (1.f/HD);
        float rs = rsqrtf(var + EPS);
        float4 gg = *(const float4*)&g2[lane*4];
        float4 bb = *(const float4*)&b2[lane*4];
        float4 o;
        o.x = f.x*rs*gg.x + bb.x; o.y = f.y*rs*gg.y + bb.y;
        o.z = f.z*rs*gg.z + bb.z; o.w = f.w*rs*gg.w + bb.w;
        *(float4*)&g_h[(row0 + r)*HD + lane*4] = o;
    }
}

// ---------------- lin: dual GEMM (Wl,Wr) + edge-cat tail ----------------
__global__ __launch_bounds__(256) void lin2_kernel(int l,
        const float* __restrict__ Wl, const float* __restrict__ bl,
        const float* __restrict__ Wr, const float* __restrict__ br,
        const float* __restrict__ We, const float* __restrict__ eemb) {
    __shared__ float4 shx[128][2];
    int tid = threadIdx.x;
    int j = tid & 127, half = tid >> 7;

    if (blockIdx.x < GB) {
        int row0 = blockIdx.x * 8;
        float v[4];
        #pragma unroll
        for (int rr = 0; rr < 4; rr++) v[rr] = g_h[(row0 + half*4 + rr)*HD + j];
        shx[j][half] = make_float4(v[0], v[1], v[2], v[3]);
        __syncthreads();

        const float* WlL = Wl + l*HD*HD;
        const float* WrL = Wr + l*HD*HD;
        float blj = bl[l*HD + j], brj = br[l*HD + j];
        float l0=blj,l1=blj,l2=blj,l3=blj;
        float r0=brj,r1=brj,r2=brj,r3=brj;
        #pragma unroll 8
        for (int k = 0; k < HD; k++) {
            float wl = WlL[k*HD + j];
            float wr = WrL[k*HD + j];
            float4 xk = shx[k][half];
            l0 = fmaf(xk.x, wl, l0); l1 = fmaf(xk.y, wl, l1);
            l2 = fmaf(xk.z, wl, l2); l3 = fmaf(xk.w, wl, l3);
            r0 = fmaf(xk.x, wr, r0); r1 = fmaf(xk.y, wr, r1);
            r2 = fmaf(xk.z, wr, r2); r3 = fmaf(xk.w, wr, r3);
        }
        int base = (row0 + half*4)*HD + j;
        g_xl[base        ] = l0; g_xl[base +   HD] = l1;
        g_xl[base + 2*HD ] = l2; g_xl[base + 3*HD] = l3;
        g_xr[base        ] = r0; g_xr[base +   HD] = r1;
        g_xr[base + 2*HD ] = r2; g_xr[base + 3*HD] = r3;
    } else {
        int row0 = (blockIdx.x - GB) * 8;
        float v[4];
        #pragma unroll
        for (int rr = 0; rr < 4; rr++) {
            int cat = row0 + half*4 + rr;
            v[rr] = (cat < 20) ? eemb[cat*HD + j] : 0.f;
        }
        shx[j][half] = make_float4(v[0], v[1], v[2], v[3]);
        __syncthreads();

        const float* WeL = We + l*HD*HD;
        float a0=0.f,a1=0.f,a2=0.f,a3=0.f;
        #pragma unroll 8
        for (int k = 0; k < HD; k++) {
            float w = WeL[k*HD + j];
            float4 xk = shx[k][half];
            a0 = fmaf(xk.x, w, a0); a1 = fmaf(xk.y, w, a1);
            a2 = fmaf(xk.z, w, a2); a3 = fmaf(xk.w, w, a3);
        }
        float acc[4] = {a0, a1, a2, a3};
        #pragma unroll
        for (int rr = 0; rr < 4; rr++) {
            int cat = row0 + half*4 + rr;
            if (cat < 20) g_ec[cat*HD + j] = acc[rr];
        }
    }
}

// ---------------- dense GATv2 attention: cp.async double-buffered tiles ----------------
__global__ void attn_kernel(const float* __restrict__ att, int l) {
    __shared__ float z[TQ][5][132];      // xr[t] + ec[cat]
    __shared__ float xt2[2][16][132];    // double-buffered s-tile of xl
    __shared__ float wsm[8*16*WROW];     // [h][j(s-lane)][t], padded rows
    int blk = blockIdx.x;
    int split = blk & (SSPLIT-1);
    int tq = (blk >> 3) % NTQ;
    int b  = blk / (SSPLIT*NTQ);
    int t0 = tq * TQ;
    int tid = threadIdx.x;
    int lane = tid & 31;
    int sl = lane & 15;
    int h  = ((tid >> 5) << 1) + (lane >> 4);
    int hc = h << 4;
    const float* attL = att + l*HD;

    int prow = tid >> 5;     // staging row base (0..3)
    int pc4  = tid & 31;     // staging float4 column
    int sbase = split * SCHUNK;

    // prologue: issue cp.async for tile 0 (overlaps z build)
    #pragma unroll
    for (int ii = 0; ii < 4; ii++) {
        int r = prow + ii*4;
        unsigned int dst = (unsigned int)__cvta_generic_to_shared(&xt2[0][r][pc4*4]);
        cpasync16(dst, g_xl + (b*NN + sbase + r)*HD + pc4*4);
    }
    CP_COMMIT();

    // build z table (float4 vectorized)
    for (int i = tid; i < TQ*5*32; i += 128) {
        int c4 = i & 31;
        int row = i >> 5;
        int t = row / 5, r = row - t*5;
        int pt = (t0 + t) & 3;
        int cat = (r < 4) ? (r*4 + pt) : (16 + pt);
        float4 xr4 = *(const float4*)(g_xr + (b*NN + t0 + t)*HD + c4*4);
        float4 ec4 = *(const float4*)(g_ec + cat*HD + c4*4);
        float4 o;
        o.x = xr4.x + ec4.x; o.y = xr4.y + ec4.y;
        o.z = xr4.z + ec4.z; o.w = xr4.w + ec4.w;
        *(float4*)&z[t][r][c4*4] = o;
    }
    float attr[16];
    #pragma unroll
    for (int c4 = 0; c4 < 4; c4++) {
        float4 a = *(const float4*)(attL + hc + c4*4);
        attr[c4*4+0] = a.x; attr[c4*4+1] = a.y; attr[c4*4+2] = a.z; attr[c4*4+3] = a.w;
    }
    float acc[TQ], dp[TQ];
    #pragma unroll
    for (int t = 0; t < TQ; t++) { acc[t] = 0.f; dp[t] = 0.f; }

    for (int sb = 0; sb < NSB; sb++) {
        int s0 = sbase + sb*16;
        CP_WAIT0();          // this thread's copies for tile sb complete
        __syncthreads();     // all threads' copies visible (also covers z on sb==0)

        // issue next tile's copies into the other buffer (overlaps compute)
        if (sb + 1 < NSB) {
            #pragma unroll
            for (int ii = 0; ii < 4; ii++) {
                int r = prow + ii*4;
                unsigned int dst = (unsigned int)__cvta_generic_to_shared(&xt2[(sb+1)&1][r][pc4*4]);
                cpasync16(dst, g_xl + (b*NN + s0 + 16 + r)*HD + pc4*4);
            }
            CP_COMMIT();
        }
        float (*xt)[132] = xt2[sb & 1];

        // phase 1: lane role = (s = s0+sl, head h); full logit in registers
        int s = s0 + sl;
        int ps = sl & 3;
        float xlr[16];
        #pragma unroll
        for (int c4 = 0; c4 < 4; c4++) {
            float4 v = *(const float4*)&xt[sl][hc + c4*4];
            xlr[c4*4+0] = v.x; xlr[c4*4+1] = v.y; xlr[c4*4+2] = v.z; xlr[c4*4+3] = v.w;
        }
        float w[TQ];
        #pragma unroll
        for (int t = 0; t < TQ; t++) {
            int r = (s == t0 + t) ? 4 : ps;
            const float* zp = &z[t][r][hc];
            float logit = 0.f;
            #pragma unroll
            for (int c4 = 0; c4 < 4; c4++) {
                float4 zz = *(const float4*)(zp + c4*4);
                float u;
                u = xlr[c4*4+0] + zz.x; u = fmaxf(u, 0.2f*u); logit = fmaf(u, attr[c4*4+0], logit);
                u = xlr[c4*4+1] + zz.y; u = fmaxf(u, 0.2f*u); logit = fmaf(u, attr[c4*4+1], logit);
                u = xlr[c4*4+2] + zz.z; u = fmaxf(u, 0.2f*u); logit = fmaf(u, attr[c4*4+2], logit);
                u = xlr[c4*4+3] + zz.w; u = fmaxf(u, 0.2f*u); logit = fmaf(u, attr[c4*4+3], logit);
            }
            float e = __expf(logit);
            w[t] = e;
            dp[t] += e;
        }
        __syncwarp();
        *(float4*)&wsm[(h*16 + sl)*WROW]     = make_float4(w[0], w[1], w[2], w[3]);
        *(float4*)&wsm[(h*16 + sl)*WROW + 4] = make_float4(w[4], w[5], w[6], w[7]);
        __syncwarp();

        // phase 2: lane role = (channel c = sl, head h)
        #pragma unroll
        for (int j = 0; j < 16; j++) {
            float xv = xt[j][hc + sl];
            float4 wa = *(const float4*)&wsm[(h*16 + j)*WROW];
            float4 wb = *(const float4*)&wsm[(h*16 + j)*WROW + 4];
            acc[0] = fmaf(wa.x, xv, acc[0]); acc[1] = fmaf(wa.y, xv, acc[1]);
            acc[2] = fmaf(wa.z, xv, acc[2]); acc[3] = fmaf(wa.w, xv, acc[3]);
            acc[4] = fmaf(wb.x, xv, acc[4]); acc[5] = fmaf(wb.y, xv, acc[5]);
            acc[6] = fmaf(wb.z, xv, acc[6]); acc[7] = fmaf(wb.w, xv, acc[7]);
        }
        __syncwarp();
    }

    // reduce denominator over the 16 s-lanes
    #pragma unroll
    for (int t = 0; t < TQ; t++) {
        float d = dp[t];
        d += __shfl_xor_sync(0xffffffffu, d, 8, 16);
        d += __shfl_xor_sync(0xffffffffu, d, 4, 16);
        d += __shfl_xor_sync(0xffffffffu, d, 2, 16);
        d += __shfl_xor_sync(0xffffffffu, d, 1, 16);
        dp[t] = d;
    }
    int base = (split*NB + b)*NN + t0;
    #pragma unroll
    for (int t = 0; t < TQ; t++) {
        g_pacc[(base + t)*HD + hc + sl] = acc[t];
        if (sl == 0) g_pd[(base + t)*8 + h] = dp[t];
    }
}

// ---------------- proj: combine partials + GEMM(W_proj) + LN + relu + residual ----------------
__global__ __launch_bounds__(256) void proj2_kernel(int l,
        const float* __restrict__ bgat, const float* __restrict__ Wp,
        const float* __restrict__ bp,
        const float* __restrict__ lng, const float* __restrict__ lnb) {
    __shared__ float4 shx[128][2];
    __shared__ float  sho[8][128];
    __shared__ float  sdeninv[8][8];
    int tid = threadIdx.x;
    int j = tid & 127, half = tid >> 7;
    int warp = tid >> 5, lane = tid & 31;
    int row0 = blockIdx.x * 8;

    if (tid < 64) {
        int r = tid >> 3, hh = tid & 7;
        float dsum = 0.f;
        #pragma unroll
        for (int sp = 0; sp < SSPLIT; sp++)
            dsum += g_pd[(sp*NROWS + row0 + r)*8 + hh];
        sdeninv[r][hh] = 1.f / dsum;
    }
    __syncthreads();

    float bgj = bgat[l*HD + j];
    int hh = j >> 4;
    float v[4];
    #pragma unroll
    for (int rr = 0; rr < 4; rr++) {
        int node = row0 + half*4 + rr;
        float a = 0.f;
        #pragma unroll
        for (int sp = 0; sp < SSPLIT; sp++)
            a += g_pacc[(sp*NROWS + node)*HD + j];
        v[rr] = a * sdeninv[half*4 + rr][hh] + bgj;
    }
    shx[j][half] = make_float4(v[0], v[1], v[2], v[3]);
    __syncthreads();

    const float* WpL = Wp + l*HD*HD;
    float bpj = bp[l*HD + j];
    float a0=bpj,a1=bpj,a2=bpj,a3=bpj;
    #pragma unroll 8
    for (int k = 0; k < HD; k++) {
        float w = WpL[k*HD + j];
        float4 xk = shx[k][half];
        a0 = fmaf(xk.x, w, a0); a1 = fmaf(xk.y, w, a1);
        a2 = fmaf(xk.z, w, a2); a3 = fmaf(xk.w, w, a3);
    }
    sho[half*4 + 0][j] = a0; sho[half*4 + 1][j] = a1;
    sho[half*4 + 2][j] = a2; sho[half*4 + 3][j] = a3;
    __syncthreads();

    {
        int r = warp;
        float4 f = *(const float4*)&sho[r][lane*4];
        float m = wsum(f.x + f.y + f.z + f.w) * (1.f/HD);
        f.x -= m; f.y -= m; f.z -= m; f.w -= m;
        float var = wsum(f.x*f.x + f.y*f.y + f.z*f.z + f.w*f.w) * (1.f/HD);
        float rs = rsqrtf(var + EPS);
        float4 gg = *(const float4*)&lng[l*HD + lane*4];
        float4 bb = *(const float4*)&lnb[l*HD + lane*4];
        float4 hres = *(const float4*)&g_h[(row0 + r)*HD + lane*4];
        float4 o;
        o.x = fmaxf(f.x*rs*gg.x + bb.x, 0.f) + hres.x;
        o.y = fmaxf(f.y*rs*gg.y + bb.y, 0.f) + hres.y;
        o.z = fmaxf(f.z*rs*gg.z + bb.z, 0.f) + hres.z;
        o.w = fmaxf(f.w*rs*gg.w + bb.w, 0.f) + hres.w;
        *(float4*)&g_h[(row0 + r)*HD + lane*4] = o;
    }
}

// ---------------- node-sum + output head ----------------
__global__ __launch_bounds__(512) void out_kernel(const float* __restrict__ Wout,
                                                  const float* __restrict__ bout,
                                                  float* __restrict__ out) {
    __shared__ float sh[4][128];
    __shared__ float tot[128];
    int b = blockIdx.x, tid = threadIdx.x;
    int q = tid >> 7, c = tid & 127;
    float a = 0.f;
    #pragma unroll 8
    for (int n = q*96; n < q*96 + 96; n++) a += g_h[(b*NN + n)*HD + c];
    sh[q][c] = a;
    __syncthreads();
    if (tid < 128) tot[tid] = sh[0][tid] + sh[1][tid] + sh[2][tid] + sh[3][tid];
    __syncthreads();
    if (tid < 10) {
        float o = bout[tid];
        #pragma unroll 16
        for (int k = 0; k < HD; k++) o = fmaf(tot[k], Wout[k*10 + tid], o);
        out[b*10 + tid] = o;
    }
}

// ---------------- launch ----------------
extern "C" void kernel_launch(void* const* d_in, const int* in_sizes, int n_in,
                              void* d_out, int out_size) {
    const int*   x    = (const int*)  d_in[0];
    const float* temb = (const float*)d_in[4];
    const float* eemb = (const float*)d_in[5];
    const float* g1   = (const float*)d_in[6];
    const float* b1   = (const float*)d_in[7];
    const float* Win  = (const float*)d_in[8];
    const float* bin  = (const float*)d_in[9];
    const float* g2   = (const float*)d_in[10];
    const float* b2   = (const float*)d_in[11];
    const float* Wl   = (const float*)d_in[12];
    const float* bl   = (const float*)d_in[13];
    const float* Wr   = (const float*)d_in[14];
    const float* br   = (const float*)d_in[15];
    const float* We   = (const float*)d_in[16];
    const float* att  = (const float*)d_in[17];
    const float* bgat = (const float*)d_in[18];
    const float* Wp   = (const float*)d_in[19];
    const float* bp   = (const float*)d_in[20];
    const float* lng  = (const float*)d_in[21];
    const float* lnb  = (const float*)d_in[22];
    const float* Wout = (const float*)d_in[23];
    const float* bout = (const float*)d_in[24];
    float* out = (float*)d_out;

    embed2_kernel<<<GB, 256>>>(x, temb, g1, b1, Win, bin, g2, b2);
    for (int l = 0; l < NL; l++) {
        lin2_kernel<<<GB + 3, 256>>>(l, Wl, bl, Wr, br, We, eemb);
        attn_kernel<<<NB*NTQ*SSPLIT, 128>>>(att, l);
        proj2_kernel<<<GB, 256>>>(l, bgat, Wp, bp, lng, lnb);
    }
    out_kernel<<<NB, 512>>>(Wout, bout, out);
}